// round 1
// baseline (speedup 1.0000x reference)
#include <cuda_runtime.h>
#include <cuda_bf16.h>
#include <cstdint>

// Problem constants
#define NN 100000
#define NE 1600000
#define NF 128
#define NC 40

// Scratch (device globals; allocation-free per harness rules)
__device__ __align__(16) float g_deg[NN];
__device__ __align__(16) float g_dinv[NN];
__device__ __align__(16) float g_t[(size_t)NN * NF];   // GEMM output (also reused for [NN,40])
__device__ __align__(16) float g_a[(size_t)NN * NF];   // aggregated activation

// ---------------------------------------------------------------------------
// Degree / norm
// ---------------------------------------------------------------------------
__global__ void k_deg_init(float* deg) {
    int i = blockIdx.x * blockDim.x + threadIdx.x;
    if (i < NN) deg[i] = 1.0f;  // self-loop
}

__global__ void k_deg(const int* __restrict__ ei, float* deg) {
    int e = blockIdx.x * blockDim.x + threadIdx.x;
    if (e < NE) atomicAdd(&deg[ei[NE + e]], 1.0f);  // dst index
}

__global__ void k_dinv(const float* __restrict__ deg, float* dinv) {
    int i = blockIdx.x * blockDim.x + threadIdx.x;
    if (i < NN) dinv[i] = rsqrtf(deg[i]);
}

// ---------------------------------------------------------------------------
// GEMM: T[M,128] = relu?(X[M,128]) @ W[128,128]
// BM=64, BN=128, BK=32, 256 threads, each thread 8x4 micro-tile.
// ---------------------------------------------------------------------------
template <bool RELU>
__global__ void k_gemm128(const float* __restrict__ X, const float* __restrict__ W,
                          float* __restrict__ T, int M) {
    __shared__ float Xs[64][33];
    __shared__ float Ws[32][128];
    const int t  = threadIdx.x;
    const int m0 = blockIdx.x * 64;
    const int r0 = (t >> 5) * 8;   // warp-uniform row group
    const int c0 = (t & 31) * 4;   // lane column group

    float acc[8][4] = {};

    for (int k0 = 0; k0 < 128; k0 += 32) {
        // Load X chunk: 64 rows x 32 K (512 float4)
#pragma unroll
        for (int i = 0; i < 2; i++) {
            int idx = t + i * 256;
            int row = idx >> 3;
            int c4  = (idx & 7) * 4;
            float4 v = make_float4(0.f, 0.f, 0.f, 0.f);
            if (m0 + row < M)
                v = *(const float4*)&X[(size_t)(m0 + row) * 128 + k0 + c4];
            if (RELU) {
                v.x = fmaxf(v.x, 0.f); v.y = fmaxf(v.y, 0.f);
                v.z = fmaxf(v.z, 0.f); v.w = fmaxf(v.w, 0.f);
            }
            Xs[row][c4 + 0] = v.x; Xs[row][c4 + 1] = v.y;
            Xs[row][c4 + 2] = v.z; Xs[row][c4 + 3] = v.w;
        }
        // Load W chunk: 32 rows x 128 cols (1024 float4)
#pragma unroll
        for (int i = 0; i < 4; i++) {
            int idx = t + i * 256;
            int row = idx >> 5;
            int c4  = (idx & 31) * 4;
            *(float4*)&Ws[row][c4] = *(const float4*)&W[(size_t)(k0 + row) * 128 + c4];
        }
        __syncthreads();
#pragma unroll
        for (int kk = 0; kk < 32; kk++) {
            float4 w = *(const float4*)&Ws[kk][c0];
#pragma unroll
            for (int i = 0; i < 8; i++) {
                float xv = Xs[r0 + i][kk];
                acc[i][0] += xv * w.x; acc[i][1] += xv * w.y;
                acc[i][2] += xv * w.z; acc[i][3] += xv * w.w;
            }
        }
        __syncthreads();
    }
#pragma unroll
    for (int i = 0; i < 8; i++) {
        int row = m0 + r0 + i;
        if (row < M)
            *(float4*)&T[(size_t)row * 128 + c0] =
                make_float4(acc[i][0], acc[i][1], acc[i][2], acc[i][3]);
    }
}

// ---------------------------------------------------------------------------
// GEMM: T[M,40] = relu?(X[M,128]) @ W[128,40]
// 128 threads, 32 rows/block; thread = (row, 10-col group)
// ---------------------------------------------------------------------------
template <bool RELU>
__global__ void k_gemm40(const float* __restrict__ X, const float* __restrict__ W,
                         float* __restrict__ T, int M) {
    __shared__ float Xs[32][129];
    __shared__ float Ws[128 * 40];
    const int t  = threadIdx.x;
    const int m0 = blockIdx.x * 32;

    // Load W: 5120 floats = 1280 float4
    for (int i = t; i < 1280; i += 128)
        *(float4*)&Ws[i * 4] = *(const float4*)&W[(size_t)i * 4];

    // Load X: 32 rows x 128 = 1024 float4
#pragma unroll
    for (int i = 0; i < 8; i++) {
        int idx = t + i * 128;
        int row = idx >> 5;
        int c4  = (idx & 31) * 4;
        float4 v = make_float4(0.f, 0.f, 0.f, 0.f);
        if (m0 + row < M)
            v = *(const float4*)&X[(size_t)(m0 + row) * 128 + c4];
        if (RELU) {
            v.x = fmaxf(v.x, 0.f); v.y = fmaxf(v.y, 0.f);
            v.z = fmaxf(v.z, 0.f); v.w = fmaxf(v.w, 0.f);
        }
        Xs[row][c4 + 0] = v.x; Xs[row][c4 + 1] = v.y;
        Xs[row][c4 + 2] = v.z; Xs[row][c4 + 3] = v.w;
    }
    __syncthreads();

    const int row = t >> 2;
    const int cg  = (t & 3) * 10;
    float acc[10] = {};
#pragma unroll 4
    for (int k = 0; k < 128; k++) {
        float xv = Xs[row][k];
#pragma unroll
        for (int j = 0; j < 10; j++)
            acc[j] += xv * Ws[k * 40 + cg + j];
    }
    int grow = m0 + row;
    if (grow < M) {
#pragma unroll
        for (int j = 0; j < 10; j++)
            T[(size_t)grow * 40 + cg + j] = acc[j];
    }
}

// ---------------------------------------------------------------------------
// Init aggregation: A = bias + dinv^2 * T  (bias broadcast + self-loop term)
// Works on float4 granularity; F4 = F/4.
// ---------------------------------------------------------------------------
__global__ void k_init_agg(const float* __restrict__ T, const float* __restrict__ dinv,
                           const float* __restrict__ bias, float* __restrict__ A,
                           int M, int F4) {
    int idx = blockIdx.x * blockDim.x + threadIdx.x;
    if (idx >= M * F4) return;
    int row = idx / F4;
    int q   = idx - row * F4;
    float d = dinv[row];
    float s = d * d;
    float4 v = ((const float4*)T)[idx];
    float4 b = ((const float4*)bias)[q];
    ((float4*)A)[idx] = make_float4(b.x + s * v.x, b.y + s * v.y,
                                    b.z + s * v.z, b.w + s * v.w);
}

// ---------------------------------------------------------------------------
// Edge scatter (F=128): 1 warp per edge, float4 vector reductions.
// ---------------------------------------------------------------------------
__global__ void k_scatter128(const int* __restrict__ ei, const float* __restrict__ dinv,
                             const float* __restrict__ T, float* __restrict__ A) {
    int g    = blockIdx.x * blockDim.x + threadIdx.x;
    int e    = g >> 5;
    int lane = g & 31;
    if (e >= NE) return;
    int src = __ldg(&ei[e]);
    int dst = __ldg(&ei[NE + e]);
    float nrm = __ldg(&dinv[src]) * __ldg(&dinv[dst]);
    float4 v = ((const float4*)T)[(size_t)src * 32 + lane];
    float* p = &A[(size_t)dst * 128 + lane * 4];
    asm volatile("red.global.add.v4.f32 [%0], {%1,%2,%3,%4};"
                 :: "l"(p), "f"(v.x * nrm), "f"(v.y * nrm),
                    "f"(v.z * nrm), "f"(v.w * nrm)
                 : "memory");
}

// ---------------------------------------------------------------------------
// Edge scatter (F=40): one float2 per thread, 20 threads per edge.
// ---------------------------------------------------------------------------
__global__ void k_scatter40(const int* __restrict__ ei, const float* __restrict__ dinv,
                            const float* __restrict__ T, float* __restrict__ A) {
    long g = blockIdx.x * (long)blockDim.x + threadIdx.x;
    if (g >= (long)NE * 20) return;
    int e = (int)(g / 20);
    int q = (int)(g - (long)e * 20);
    int src = __ldg(&ei[e]);
    int dst = __ldg(&ei[NE + e]);
    float nrm = __ldg(&dinv[src]) * __ldg(&dinv[dst]);
    float2 v = ((const float2*)T)[(size_t)src * 20 + q];
    float* p = &A[(size_t)dst * 40 + q * 2];
    asm volatile("red.global.add.v2.f32 [%0], {%1,%2};"
                 :: "l"(p), "f"(v.x * nrm), "f"(v.y * nrm)
                 : "memory");
}

// ---------------------------------------------------------------------------
// relu copy for x_latent output
// ---------------------------------------------------------------------------
__global__ void k_relu_copy(const float* __restrict__ A, float* __restrict__ O) {
    int idx = blockIdx.x * blockDim.x + threadIdx.x;
    if (idx >= NN * 32) return;
    float4 v = ((const float4*)A)[idx];
    ((float4*)O)[idx] = make_float4(fmaxf(v.x, 0.f), fmaxf(v.y, 0.f),
                                    fmaxf(v.z, 0.f), fmaxf(v.w, 0.f));
}

// ---------------------------------------------------------------------------
// Launch
// ---------------------------------------------------------------------------
extern "C" void kernel_launch(void* const* d_in, const int* in_sizes, int n_in,
                              void* d_out, int out_size) {
    const float* x  = (const float*)d_in[0];
    const int*   ei = (const int*)d_in[1];
    const float* W1 = (const float*)d_in[2];
    const float* b1 = (const float*)d_in[3];
    const float* W2 = (const float*)d_in[4];
    const float* b2 = (const float*)d_in[5];
    const float* W3 = (const float*)d_in[6];
    const float* b3 = (const float*)d_in[7];
    const float* W4 = (const float*)d_in[8];
    const float* b4 = (const float*)d_in[9];

    float* out    = (float*)d_out;            // [NN, 40]
    float* latent = out + (size_t)NN * NC;    // [NN, 128]

    void *pdeg, *pdinv, *pt, *pa;
    cudaGetSymbolAddress(&pdeg,  g_deg);
    cudaGetSymbolAddress(&pdinv, g_dinv);
    cudaGetSymbolAddress(&pt,    g_t);
    cudaGetSymbolAddress(&pa,    g_a);
    float* deg  = (float*)pdeg;
    float* dinv = (float*)pdinv;
    float* t    = (float*)pt;
    float* a    = (float*)pa;

    const int B = 256;

    // degree + normalization
    k_deg_init<<<(NN + B - 1) / B, B>>>(deg);
    k_deg<<<(NE + B - 1) / B, B>>>(ei, deg);
    k_dinv<<<(NN + B - 1) / B, B>>>(deg, dinv);

    const int gemm128_grid = (NN + 63) / 64;
    const int init128_grid = (NN * 32 + B - 1) / B;
    const int scat128_grid = (NE * 32 + B - 1) / B;  // 32 threads per edge

    // Layer 1: x -> a
    k_gemm128<false><<<gemm128_grid, 256>>>(x, W1, t, NN);
    k_init_agg<<<init128_grid, B>>>(t, dinv, b1, a, NN, 32);
    k_scatter128<<<scat128_grid, B>>>(ei, dinv, t, a);

    // Layer 2: relu(a) -> a
    k_gemm128<true><<<gemm128_grid, 256>>>(a, W2, t, NN);
    k_init_agg<<<init128_grid, B>>>(t, dinv, b2, a, NN, 32);
    k_scatter128<<<scat128_grid, B>>>(ei, dinv, t, a);

    // Layer 3: relu(a) -> a
    k_gemm128<true><<<gemm128_grid, 256>>>(a, W3, t, NN);
    k_init_agg<<<init128_grid, B>>>(t, dinv, b3, a, NN, 32);
    k_scatter128<<<scat128_grid, B>>>(ei, dinv, t, a);

    // x_latent = relu(a)
    k_relu_copy<<<(NN * 32 + B - 1) / B, B>>>(a, latent);

    // Layer 4: relu(a) @ W4 -> out (40 classes)
    k_gemm40<true><<<(NN + 31) / 32, 128>>>(a, W4, t, NN);
    k_init_agg<<<(NN * 10 + B - 1) / B, B>>>(t, dinv, b4, out, NN, 10);
    {
        long total = (long)NE * 20;
        int grid = (int)((total + B - 1) / B);
        k_scatter40<<<grid, B>>>(ei, dinv, t, out);
    }
}

// round 2
// speedup vs baseline: 1.8113x; 1.8113x over previous
#include <cuda_runtime.h>
#include <cuda_bf16.h>
#include <cstdint>

#define NN 100000
#define NE 1600000
#define NF 128
#define NC 40
#define NB_SCAN ((NN + 1023) / 1024)

// Scratch (device globals)
__device__ __align__(16) float g_dinv[NN];
__device__ __align__(16) float g_t[(size_t)NN * NF];   // Y = dinv * (X@W)
__device__ __align__(16) float g_a[(size_t)NN * NF];   // aggregated activation
__device__ int g_cnt[NN];
__device__ int g_rs[NN + 1];       // CSR row starts (by dst)
__device__ int g_cursor[NN];
__device__ int g_csr[NE];          // src indices grouped by dst
__device__ int g_bsum[NB_SCAN];
__device__ int g_boff[NB_SCAN];

// ---------------------------------------------------------------------------
// CSR build
// ---------------------------------------------------------------------------
__global__ void k_zero(int* cnt) {
    int i = blockIdx.x * blockDim.x + threadIdx.x;
    if (i < NN) cnt[i] = 0;
}

__global__ void k_count(const int* __restrict__ ei, int* cnt) {
    int e = blockIdx.x * blockDim.x + threadIdx.x;
    if (e < NE) atomicAdd(&cnt[ei[NE + e]], 1);
}

__global__ void k_dinv(const int* __restrict__ cnt, float* dinv) {
    int i = blockIdx.x * blockDim.x + threadIdx.x;
    if (i < NN) dinv[i] = rsqrtf((float)(cnt[i] + 1));  // +1 self loop
}

__global__ void k_scan1(const int* __restrict__ cnt, int* rs, int* bsum) {
    __shared__ int s[1024];
    int i = blockIdx.x * 1024 + threadIdx.x;
    int v = (i < NN) ? cnt[i] : 0;
    s[threadIdx.x] = v;
    __syncthreads();
#pragma unroll
    for (int o = 1; o < 1024; o <<= 1) {
        int t = (threadIdx.x >= o) ? s[threadIdx.x - o] : 0;
        __syncthreads();
        s[threadIdx.x] += t;
        __syncthreads();
    }
    if (i < NN) rs[i] = s[threadIdx.x] - v;  // exclusive
    if (threadIdx.x == 1023) bsum[blockIdx.x] = s[1023];
}

__global__ void k_scan2(const int* __restrict__ bsum, int* boff) {
    __shared__ int s[NB_SCAN];
    if (threadIdx.x < NB_SCAN) s[threadIdx.x] = bsum[threadIdx.x];
    __syncthreads();
    if (threadIdx.x == 0) {
        int run = 0;
        for (int i = 0; i < NB_SCAN; i++) { int v = s[i]; s[i] = run; run += v; }
    }
    __syncthreads();
    if (threadIdx.x < NB_SCAN) boff[threadIdx.x] = s[threadIdx.x];
}

__global__ void k_scan3(int* rs, int* cursor, const int* __restrict__ boff) {
    int i = blockIdx.x * blockDim.x + threadIdx.x;
    if (i < NN) {
        int v = rs[i] + boff[i >> 10];
        rs[i] = v;
        cursor[i] = v;
    }
    if (i == 0) rs[NN] = NE;
}

__global__ void k_fill(const int* __restrict__ ei, int* cursor, int* csr) {
    int e = blockIdx.x * blockDim.x + threadIdx.x;
    if (e >= NE) return;
    int src = ei[e];
    int dst = ei[NE + e];
    int pos = atomicAdd(&cursor[dst], 1);
    csr[pos] = src;
}

// ---------------------------------------------------------------------------
// GEMM: Y[M,128] = dinv[m] * (relu?(X[M,128]) @ W[128,128])
// ---------------------------------------------------------------------------
template <bool RELU>
__global__ void k_gemm128(const float* __restrict__ X, const float* __restrict__ W,
                          const float* __restrict__ dinv, float* __restrict__ Y, int M) {
    __shared__ float Xs[64][33];
    __shared__ float Ws[32][128];
    const int t  = threadIdx.x;
    const int m0 = blockIdx.x * 64;
    const int r0 = (t >> 5) * 8;
    const int c0 = (t & 31) * 4;

    float acc[8][4] = {};

    for (int k0 = 0; k0 < 128; k0 += 32) {
#pragma unroll
        for (int i = 0; i < 2; i++) {
            int idx = t + i * 256;
            int row = idx >> 3;
            int c4  = (idx & 7) * 4;
            float4 v = make_float4(0.f, 0.f, 0.f, 0.f);
            if (m0 + row < M)
                v = *(const float4*)&X[(size_t)(m0 + row) * 128 + k0 + c4];
            if (RELU) {
                v.x = fmaxf(v.x, 0.f); v.y = fmaxf(v.y, 0.f);
                v.z = fmaxf(v.z, 0.f); v.w = fmaxf(v.w, 0.f);
            }
            Xs[row][c4 + 0] = v.x; Xs[row][c4 + 1] = v.y;
            Xs[row][c4 + 2] = v.z; Xs[row][c4 + 3] = v.w;
        }
#pragma unroll
        for (int i = 0; i < 4; i++) {
            int idx = t + i * 256;
            int row = idx >> 5;
            int c4  = (idx & 31) * 4;
            *(float4*)&Ws[row][c4] = *(const float4*)&W[(size_t)(k0 + row) * 128 + c4];
        }
        __syncthreads();
#pragma unroll
        for (int kk = 0; kk < 32; kk++) {
            float4 w = *(const float4*)&Ws[kk][c0];
#pragma unroll
            for (int i = 0; i < 8; i++) {
                float xv = Xs[r0 + i][kk];
                acc[i][0] += xv * w.x; acc[i][1] += xv * w.y;
                acc[i][2] += xv * w.z; acc[i][3] += xv * w.w;
            }
        }
        __syncthreads();
    }
#pragma unroll
    for (int i = 0; i < 8; i++) {
        int row = m0 + r0 + i;
        if (row < M) {
            float d = __ldg(&dinv[row]);
            *(float4*)&Y[(size_t)row * 128 + c0] =
                make_float4(d * acc[i][0], d * acc[i][1], d * acc[i][2], d * acc[i][3]);
        }
    }
}

// ---------------------------------------------------------------------------
// GEMM: Y[M,40] = dinv[m] * (relu(X[M,128]) @ W[128,40])
// ---------------------------------------------------------------------------
__global__ void k_gemm40(const float* __restrict__ X, const float* __restrict__ W,
                         const float* __restrict__ dinv, float* __restrict__ Y, int M) {
    __shared__ float Xs[32][129];
    __shared__ float Ws[128 * 40];
    const int t  = threadIdx.x;
    const int m0 = blockIdx.x * 32;

    for (int i = t; i < 1280; i += 128)
        *(float4*)&Ws[i * 4] = *(const float4*)&W[(size_t)i * 4];

#pragma unroll
    for (int i = 0; i < 8; i++) {
        int idx = t + i * 128;
        int row = idx >> 5;
        int c4  = (idx & 31) * 4;
        float4 v = make_float4(0.f, 0.f, 0.f, 0.f);
        if (m0 + row < M)
            v = *(const float4*)&X[(size_t)(m0 + row) * 128 + c4];
        v.x = fmaxf(v.x, 0.f); v.y = fmaxf(v.y, 0.f);
        v.z = fmaxf(v.z, 0.f); v.w = fmaxf(v.w, 0.f);
        Xs[row][c4 + 0] = v.x; Xs[row][c4 + 1] = v.y;
        Xs[row][c4 + 2] = v.z; Xs[row][c4 + 3] = v.w;
    }
    __syncthreads();

    const int row = t >> 2;
    const int cg  = (t & 3) * 10;
    float acc[10] = {};
#pragma unroll 4
    for (int k = 0; k < 128; k++) {
        float xv = Xs[row][k];
#pragma unroll
        for (int j = 0; j < 10; j++)
            acc[j] += xv * Ws[k * 40 + cg + j];
    }
    int grow = m0 + row;
    if (grow < M) {
        float d = __ldg(&dinv[grow]);
#pragma unroll
        for (int j = 0; j < 10; j++)
            Y[(size_t)grow * 40 + cg + j] = d * acc[j];
    }
}

// ---------------------------------------------------------------------------
// Aggregation gather (F=128): warp per node.
// A[i] = b + dinv[i] * (Y[i] + sum_{src in N(i)} Y[src]); optional relu->latent
// ---------------------------------------------------------------------------
template <bool WRITE_LATENT>
__global__ void k_agg128(const int* __restrict__ rs, const int* __restrict__ csr,
                         const float* __restrict__ Y, const float* __restrict__ dinv,
                         const float* __restrict__ bias, float* __restrict__ A,
                         float* __restrict__ latent) {
    int node = blockIdx.x * (blockDim.x >> 5) + (threadIdx.x >> 5);
    if (node >= NN) return;
    int lane = threadIdx.x & 31;
    int beg = __ldg(&rs[node]);
    int end = __ldg(&rs[node + 1]);

    const float4* Y4 = (const float4*)Y;
    float4 acc = Y4[(size_t)node * 32 + lane];  // self loop (already dinv-scaled)

    int j = beg;
    for (; j + 4 <= end; j += 4) {
        int s0 = __ldg(&csr[j]);
        int s1 = __ldg(&csr[j + 1]);
        int s2 = __ldg(&csr[j + 2]);
        int s3 = __ldg(&csr[j + 3]);
        float4 v0 = Y4[(size_t)s0 * 32 + lane];
        float4 v1 = Y4[(size_t)s1 * 32 + lane];
        float4 v2 = Y4[(size_t)s2 * 32 + lane];
        float4 v3 = Y4[(size_t)s3 * 32 + lane];
        acc.x += (v0.x + v1.x) + (v2.x + v3.x);
        acc.y += (v0.y + v1.y) + (v2.y + v3.y);
        acc.z += (v0.z + v1.z) + (v2.z + v3.z);
        acc.w += (v0.w + v1.w) + (v2.w + v3.w);
    }
    for (; j < end; j++) {
        int s = __ldg(&csr[j]);
        float4 v = Y4[(size_t)s * 32 + lane];
        acc.x += v.x; acc.y += v.y; acc.z += v.z; acc.w += v.w;
    }

    float d = __ldg(&dinv[node]);
    float4 b = ((const float4*)bias)[lane];
    float4 o = make_float4(b.x + d * acc.x, b.y + d * acc.y,
                           b.z + d * acc.z, b.w + d * acc.w);
    ((float4*)A)[(size_t)node * 32 + lane] = o;
    if (WRITE_LATENT) {
        ((float4*)latent)[(size_t)node * 32 + lane] =
            make_float4(fmaxf(o.x, 0.f), fmaxf(o.y, 0.f),
                        fmaxf(o.z, 0.f), fmaxf(o.w, 0.f));
    }
}

// ---------------------------------------------------------------------------
// Aggregation gather (F=40): warp per node, lanes 0..19 hold float2.
// ---------------------------------------------------------------------------
__global__ void k_agg40(const int* __restrict__ rs, const int* __restrict__ csr,
                        const float* __restrict__ Y, const float* __restrict__ dinv,
                        const float* __restrict__ bias, float* __restrict__ A) {
    int node = blockIdx.x * (blockDim.x >> 5) + (threadIdx.x >> 5);
    if (node >= NN) return;
    int lane = threadIdx.x & 31;
    int beg = __ldg(&rs[node]);
    int end = __ldg(&rs[node + 1]);
    bool act = lane < 20;

    const float2* Y2 = (const float2*)Y;
    float2 acc = make_float2(0.f, 0.f);
    if (act) acc = Y2[(size_t)node * 20 + lane];

    int j = beg;
    for (; j + 2 <= end; j += 2) {
        int s0 = __ldg(&csr[j]);
        int s1 = __ldg(&csr[j + 1]);
        if (act) {
            float2 v0 = Y2[(size_t)s0 * 20 + lane];
            float2 v1 = Y2[(size_t)s1 * 20 + lane];
            acc.x += v0.x + v1.x;
            acc.y += v0.y + v1.y;
        }
    }
    for (; j < end; j++) {
        int s = __ldg(&csr[j]);
        if (act) {
            float2 v = Y2[(size_t)s * 20 + lane];
            acc.x += v.x; acc.y += v.y;
        }
    }
    if (act) {
        float d = __ldg(&dinv[node]);
        float2 b = ((const float2*)bias)[lane];
        ((float2*)A)[(size_t)node * 20 + lane] =
            make_float2(b.x + d * acc.x, b.y + d * acc.y);
    }
}

// ---------------------------------------------------------------------------
// Launch
// ---------------------------------------------------------------------------
extern "C" void kernel_launch(void* const* d_in, const int* in_sizes, int n_in,
                              void* d_out, int out_size) {
    const float* x  = (const float*)d_in[0];
    const int*   ei = (const int*)d_in[1];
    const float* W1 = (const float*)d_in[2];
    const float* b1 = (const float*)d_in[3];
    const float* W2 = (const float*)d_in[4];
    const float* b2 = (const float*)d_in[5];
    const float* W3 = (const float*)d_in[6];
    const float* b3 = (const float*)d_in[7];
    const float* W4 = (const float*)d_in[8];
    const float* b4 = (const float*)d_in[9];

    float* out    = (float*)d_out;            // [NN, 40]
    float* latent = out + (size_t)NN * NC;    // [NN, 128]

    void *pdinv, *pt, *pa, *pcnt, *prs, *pcur, *pcsr, *pbs, *pbo;
    cudaGetSymbolAddress(&pdinv, g_dinv);
    cudaGetSymbolAddress(&pt,    g_t);
    cudaGetSymbolAddress(&pa,    g_a);
    cudaGetSymbolAddress(&pcnt,  g_cnt);
    cudaGetSymbolAddress(&prs,   g_rs);
    cudaGetSymbolAddress(&pcur,  g_cursor);
    cudaGetSymbolAddress(&pcsr,  g_csr);
    cudaGetSymbolAddress(&pbs,   g_bsum);
    cudaGetSymbolAddress(&pbo,   g_boff);
    float* dinv = (float*)pdinv;
    float* t    = (float*)pt;
    float* a    = (float*)pa;
    int* cnt    = (int*)pcnt;
    int* rs     = (int*)prs;
    int* cursor = (int*)pcur;
    int* csr    = (int*)pcsr;
    int* bsum   = (int*)pbs;
    int* boff   = (int*)pbo;

    const int B = 256;

    // --- CSR build + normalization ---
    k_zero<<<(NN + B - 1) / B, B>>>(cnt);
    k_count<<<(NE + B - 1) / B, B>>>(ei, cnt);
    k_dinv<<<(NN + B - 1) / B, B>>>(cnt, dinv);
    k_scan1<<<NB_SCAN, 1024>>>(cnt, rs, bsum);
    k_scan2<<<1, 128>>>(bsum, boff);
    k_scan3<<<(NN + B - 1) / B, B>>>(rs, cursor, boff);
    k_fill<<<(NE + B - 1) / B, B>>>(ei, cursor, csr);

    const int gemm128_grid = (NN + 63) / 64;
    const int agg_grid     = (NN + 7) / 8;   // 8 warps/block

    // Layer 1
    k_gemm128<false><<<gemm128_grid, 256>>>(x, W1, dinv, t, NN);
    k_agg128<false><<<agg_grid, 256>>>(rs, csr, t, dinv, b1, a, nullptr);
    // Layer 2
    k_gemm128<true><<<gemm128_grid, 256>>>(a, W2, dinv, t, NN);
    k_agg128<false><<<agg_grid, 256>>>(rs, csr, t, dinv, b2, a, nullptr);
    // Layer 3 (+ latent = relu(a))
    k_gemm128<true><<<gemm128_grid, 256>>>(a, W3, dinv, t, NN);
    k_agg128<true><<<agg_grid, 256>>>(rs, csr, t, dinv, b3, a, latent);
    // Layer 4
    k_gemm40<<<(NN + 31) / 32, 128>>>(a, W4, dinv, t, NN);
    k_agg40<<<agg_grid, 256>>>(rs, csr, t, dinv, b4, out);
}

// round 3
// speedup vs baseline: 1.8563x; 1.0249x over previous
#include <cuda_runtime.h>
#include <cuda_bf16.h>
#include <cstdint>

#define NN 100000
#define NE 1600000
#define NF 128
#define NC 40
#define NB_SCAN ((NN + 1023) / 1024)

// Scratch (device globals)
__device__ __align__(16) float g_dinv[NN];
__device__ __align__(16) float g_t[(size_t)NN * NF];   // Y = dinv * (X@W)
__device__ __align__(16) float g_a[(size_t)NN * NF];   // aggregated activation
__device__ int g_cnt[NN];
__device__ int g_rs[NN + 1];       // CSR row starts (by dst)
__device__ int g_cursor[NN];
__device__ int g_csr[NE];          // src indices grouped by dst
__device__ int g_bsum[NB_SCAN];
__device__ int g_boff[NB_SCAN];

// ---------------------------------------------------------------------------
// Packed fp32x2 helpers (FFMA2 — only reachable via PTX, 2x fp32 pipe)
// ---------------------------------------------------------------------------
__device__ __forceinline__ unsigned long long pack2(float x, float y) {
    unsigned long long r;
    asm("mov.b64 %0, {%1, %2};" : "=l"(r) : "f"(x), "f"(y));
    return r;
}
__device__ __forceinline__ void ffma2(unsigned long long& d,
                                      unsigned long long a, unsigned long long b) {
    asm("fma.rn.f32x2 %0, %1, %2, %0;" : "+l"(d) : "l"(a), "l"(b));
}
__device__ __forceinline__ float2 unpack2(unsigned long long v) {
    float2 r;
    asm("mov.b64 {%0, %1}, %2;" : "=f"(r.x), "=f"(r.y) : "l"(v));
    return r;
}

// ---------------------------------------------------------------------------
// CSR build
// ---------------------------------------------------------------------------
__global__ void k_zero(int* cnt) {
    int i = blockIdx.x * blockDim.x + threadIdx.x;
    if (i < NN) cnt[i] = 0;
}

__global__ void k_count(const int* __restrict__ ei, int* cnt) {
    int e = blockIdx.x * blockDim.x + threadIdx.x;
    if (e < NE) atomicAdd(&cnt[ei[NE + e]], 1);
}

__global__ void k_dinv(const int* __restrict__ cnt, float* dinv) {
    int i = blockIdx.x * blockDim.x + threadIdx.x;
    if (i < NN) dinv[i] = rsqrtf((float)(cnt[i] + 1));  // +1 self loop
}

__global__ void k_scan1(const int* __restrict__ cnt, int* rs, int* bsum) {
    __shared__ int s[1024];
    int i = blockIdx.x * 1024 + threadIdx.x;
    int v = (i < NN) ? cnt[i] : 0;
    s[threadIdx.x] = v;
    __syncthreads();
#pragma unroll
    for (int o = 1; o < 1024; o <<= 1) {
        int t = (threadIdx.x >= o) ? s[threadIdx.x - o] : 0;
        __syncthreads();
        s[threadIdx.x] += t;
        __syncthreads();
    }
    if (i < NN) rs[i] = s[threadIdx.x] - v;  // exclusive
    if (threadIdx.x == 1023) bsum[blockIdx.x] = s[1023];
}

__global__ void k_scan2(const int* __restrict__ bsum, int* boff) {
    __shared__ int s[NB_SCAN];
    if (threadIdx.x < NB_SCAN) s[threadIdx.x] = bsum[threadIdx.x];
    __syncthreads();
    if (threadIdx.x == 0) {
        int run = 0;
        for (int i = 0; i < NB_SCAN; i++) { int v = s[i]; s[i] = run; run += v; }
    }
    __syncthreads();
    if (threadIdx.x < NB_SCAN) boff[threadIdx.x] = s[threadIdx.x];
}

__global__ void k_scan3(int* rs, int* cursor, const int* __restrict__ boff) {
    int i = blockIdx.x * blockDim.x + threadIdx.x;
    if (i < NN) {
        int v = rs[i] + boff[i >> 10];
        rs[i] = v;
        cursor[i] = v;
    }
    if (i == 0) rs[NN] = NE;
}

__global__ void k_fill(const int* __restrict__ ei, int* cursor, int* csr) {
    int e = blockIdx.x * blockDim.x + threadIdx.x;
    if (e >= NE) return;
    int src = ei[e];
    int dst = ei[NE + e];
    int pos = atomicAdd(&cursor[dst], 1);
    csr[pos] = src;
}

// ---------------------------------------------------------------------------
// GEMM: Y[M,128] = dinv[m] * (relu?(X[M,128]) @ W[128,128])  — f32x2 inner
// ---------------------------------------------------------------------------
template <bool RELU>
__global__ void k_gemm128(const float* __restrict__ X, const float* __restrict__ W,
                          const float* __restrict__ dinv, float* __restrict__ Y, int M) {
    __shared__ float Xs[64][33];
    __shared__ float Ws[32][128];
    const int t  = threadIdx.x;
    const int m0 = blockIdx.x * 64;
    const int r0 = (t >> 5) * 8;
    const int c0 = (t & 31) * 4;

    unsigned long long acc2[8][2] = {};  // two f32x2 per row = 4 N-cols

    for (int k0 = 0; k0 < 128; k0 += 32) {
#pragma unroll
        for (int i = 0; i < 2; i++) {
            int idx = t + i * 256;
            int row = idx >> 3;
            int c4  = (idx & 7) * 4;
            float4 v = make_float4(0.f, 0.f, 0.f, 0.f);
            if (m0 + row < M)
                v = *(const float4*)&X[(size_t)(m0 + row) * 128 + k0 + c4];
            if (RELU) {
                v.x = fmaxf(v.x, 0.f); v.y = fmaxf(v.y, 0.f);
                v.z = fmaxf(v.z, 0.f); v.w = fmaxf(v.w, 0.f);
            }
            Xs[row][c4 + 0] = v.x; Xs[row][c4 + 1] = v.y;
            Xs[row][c4 + 2] = v.z; Xs[row][c4 + 3] = v.w;
        }
#pragma unroll
        for (int i = 0; i < 4; i++) {
            int idx = t + i * 256;
            int row = idx >> 5;
            int c4  = (idx & 31) * 4;
            *(float4*)&Ws[row][c4] = *(const float4*)&W[(size_t)(k0 + row) * 128 + c4];
        }
        __syncthreads();
#pragma unroll
        for (int kk = 0; kk < 32; kk++) {
            const unsigned long long* wp = (const unsigned long long*)&Ws[kk][c0];
            unsigned long long w01 = wp[0];
            unsigned long long w23 = wp[1];
#pragma unroll
            for (int i = 0; i < 8; i++) {
                float xv = Xs[r0 + i][kk];
                unsigned long long xp = pack2(xv, xv);
                ffma2(acc2[i][0], xp, w01);
                ffma2(acc2[i][1], xp, w23);
            }
        }
        __syncthreads();
    }
#pragma unroll
    for (int i = 0; i < 8; i++) {
        int row = m0 + r0 + i;
        if (row < M) {
            float d = __ldg(&dinv[row]);
            float2 a0 = unpack2(acc2[i][0]);
            float2 a1 = unpack2(acc2[i][1]);
            *(float4*)&Y[(size_t)row * 128 + c0] =
                make_float4(d * a0.x, d * a0.y, d * a1.x, d * a1.y);
        }
    }
}

// ---------------------------------------------------------------------------
// GEMM: Y[M,40] = dinv[m] * (relu(X[M,128]) @ W[128,40])  — f32x2 inner
// ---------------------------------------------------------------------------
__global__ void k_gemm40(const float* __restrict__ X, const float* __restrict__ W,
                         const float* __restrict__ dinv, float* __restrict__ Y, int M) {
    __shared__ float Xs[32][129];
    __shared__ float Ws[128 * 40];
    const int t  = threadIdx.x;
    const int m0 = blockIdx.x * 32;

    for (int i = t; i < 1280; i += 128)
        *(float4*)&Ws[i * 4] = *(const float4*)&W[(size_t)i * 4];

#pragma unroll
    for (int i = 0; i < 8; i++) {
        int idx = t + i * 128;
        int row = idx >> 5;
        int c4  = (idx & 31) * 4;
        float4 v = make_float4(0.f, 0.f, 0.f, 0.f);
        if (m0 + row < M)
            v = *(const float4*)&X[(size_t)(m0 + row) * 128 + c4];
        v.x = fmaxf(v.x, 0.f); v.y = fmaxf(v.y, 0.f);
        v.z = fmaxf(v.z, 0.f); v.w = fmaxf(v.w, 0.f);
        Xs[row][c4 + 0] = v.x; Xs[row][c4 + 1] = v.y;
        Xs[row][c4 + 2] = v.z; Xs[row][c4 + 3] = v.w;
    }
    __syncthreads();

    const int row = t >> 2;
    const int cg  = (t & 3) * 10;
    unsigned long long acc2[5] = {};
#pragma unroll 4
    for (int k = 0; k < 128; k++) {
        float xv = Xs[row][k];
        unsigned long long xp = pack2(xv, xv);
        const unsigned long long* wp = (const unsigned long long*)&Ws[k * 40 + cg];
#pragma unroll
        for (int j = 0; j < 5; j++)
            ffma2(acc2[j], xp, wp[j]);
    }
    int grow = m0 + row;
    if (grow < M) {
        float d = __ldg(&dinv[grow]);
#pragma unroll
        for (int j = 0; j < 5; j++) {
            float2 a = unpack2(acc2[j]);
            *(float2*)&Y[(size_t)grow * 40 + cg + j * 2] =
                make_float2(d * a.x, d * a.y);
        }
    }
}

// ---------------------------------------------------------------------------
// Aggregation gather (F=128): warp per node.
// A[i] = b + dinv[i] * (Y[i] + sum_{src in N(i)} Y[src]); optional relu->latent
// ---------------------------------------------------------------------------
template <bool WRITE_LATENT>
__global__ void k_agg128(const int* __restrict__ rs, const int* __restrict__ csr,
                         const float* __restrict__ Y, const float* __restrict__ dinv,
                         const float* __restrict__ bias, float* __restrict__ A,
                         float* __restrict__ latent) {
    int node = blockIdx.x * (blockDim.x >> 5) + (threadIdx.x >> 5);
    if (node >= NN) return;
    int lane = threadIdx.x & 31;
    int beg = __ldg(&rs[node]);
    int end = __ldg(&rs[node + 1]);

    const float4* Y4 = (const float4*)Y;
    float4 acc = Y4[(size_t)node * 32 + lane];  // self loop (already dinv-scaled)

    int j = beg;
    for (; j + 4 <= end; j += 4) {
        int s0 = __ldg(&csr[j]);
        int s1 = __ldg(&csr[j + 1]);
        int s2 = __ldg(&csr[j + 2]);
        int s3 = __ldg(&csr[j + 3]);
        float4 v0 = Y4[(size_t)s0 * 32 + lane];
        float4 v1 = Y4[(size_t)s1 * 32 + lane];
        float4 v2 = Y4[(size_t)s2 * 32 + lane];
        float4 v3 = Y4[(size_t)s3 * 32 + lane];
        acc.x += (v0.x + v1.x) + (v2.x + v3.x);
        acc.y += (v0.y + v1.y) + (v2.y + v3.y);
        acc.z += (v0.z + v1.z) + (v2.z + v3.z);
        acc.w += (v0.w + v1.w) + (v2.w + v3.w);
    }
    for (; j < end; j++) {
        int s = __ldg(&csr[j]);
        float4 v = Y4[(size_t)s * 32 + lane];
        acc.x += v.x; acc.y += v.y; acc.z += v.z; acc.w += v.w;
    }

    float d = __ldg(&dinv[node]);
    float4 b = ((const float4*)bias)[lane];
    float4 o = make_float4(b.x + d * acc.x, b.y + d * acc.y,
                           b.z + d * acc.z, b.w + d * acc.w);
    ((float4*)A)[(size_t)node * 32 + lane] = o;
    if (WRITE_LATENT) {
        ((float4*)latent)[(size_t)node * 32 + lane] =
            make_float4(fmaxf(o.x, 0.f), fmaxf(o.y, 0.f),
                        fmaxf(o.z, 0.f), fmaxf(o.w, 0.f));
    }
}

// ---------------------------------------------------------------------------
// Aggregation gather (F=40): warp per node, lanes 0..19 hold float2.
// ---------------------------------------------------------------------------
__global__ void k_agg40(const int* __restrict__ rs, const int* __restrict__ csr,
                        const float* __restrict__ Y, const float* __restrict__ dinv,
                        const float* __restrict__ bias, float* __restrict__ A) {
    int node = blockIdx.x * (blockDim.x >> 5) + (threadIdx.x >> 5);
    if (node >= NN) return;
    int lane = threadIdx.x & 31;
    int beg = __ldg(&rs[node]);
    int end = __ldg(&rs[node + 1]);
    bool act = lane < 20;

    const float2* Y2 = (const float2*)Y;
    float2 acc = make_float2(0.f, 0.f);
    if (act) acc = Y2[(size_t)node * 20 + lane];

    int j = beg;
    for (; j + 2 <= end; j += 2) {
        int s0 = __ldg(&csr[j]);
        int s1 = __ldg(&csr[j + 1]);
        if (act) {
            float2 v0 = Y2[(size_t)s0 * 20 + lane];
            float2 v1 = Y2[(size_t)s1 * 20 + lane];
            acc.x += v0.x + v1.x;
            acc.y += v0.y + v1.y;
        }
    }
    for (; j < end; j++) {
        int s = __ldg(&csr[j]);
        if (act) {
            float2 v = Y2[(size_t)s * 20 + lane];
            acc.x += v.x; acc.y += v.y;
        }
    }
    if (act) {
        float d = __ldg(&dinv[node]);
        float2 b = ((const float2*)bias)[lane];
        ((float2*)A)[(size_t)node * 20 + lane] =
            make_float2(b.x + d * acc.x, b.y + d * acc.y);
    }
}

// ---------------------------------------------------------------------------
// Launch
// ---------------------------------------------------------------------------
extern "C" void kernel_launch(void* const* d_in, const int* in_sizes, int n_in,
                              void* d_out, int out_size) {
    const float* x  = (const float*)d_in[0];
    const int*   ei = (const int*)d_in[1];
    const float* W1 = (const float*)d_in[2];
    const float* b1 = (const float*)d_in[3];
    const float* W2 = (const float*)d_in[4];
    const float* b2 = (const float*)d_in[5];
    const float* W3 = (const float*)d_in[6];
    const float* b3 = (const float*)d_in[7];
    const float* W4 = (const float*)d_in[8];
    const float* b4 = (const float*)d_in[9];

    float* out    = (float*)d_out;            // [NN, 40]
    float* latent = out + (size_t)NN * NC;    // [NN, 128]

    void *pdinv, *pt, *pa, *pcnt, *prs, *pcur, *pcsr, *pbs, *pbo;
    cudaGetSymbolAddress(&pdinv, g_dinv);
    cudaGetSymbolAddress(&pt,    g_t);
    cudaGetSymbolAddress(&pa,    g_a);
    cudaGetSymbolAddress(&pcnt,  g_cnt);
    cudaGetSymbolAddress(&prs,   g_rs);
    cudaGetSymbolAddress(&pcur,  g_cursor);
    cudaGetSymbolAddress(&pcsr,  g_csr);
    cudaGetSymbolAddress(&pbs,   g_bsum);
    cudaGetSymbolAddress(&pbo,   g_boff);
    float* dinv = (float*)pdinv;
    float* t    = (float*)pt;
    float* a    = (float*)pa;
    int* cnt    = (int*)pcnt;
    int* rs     = (int*)prs;
    int* cursor = (int*)pcur;
    int* csr    = (int*)pcsr;
    int* bsum   = (int*)pbs;
    int* boff   = (int*)pbo;

    const int B = 256;

    // --- CSR build + normalization ---
    k_zero<<<(NN + B - 1) / B, B>>>(cnt);
    k_count<<<(NE + B - 1) / B, B>>>(ei, cnt);
    k_dinv<<<(NN + B - 1) / B, B>>>(cnt, dinv);
    k_scan1<<<NB_SCAN, 1024>>>(cnt, rs, bsum);
    k_scan2<<<1, 128>>>(bsum, boff);
    k_scan3<<<(NN + B - 1) / B, B>>>(rs, cursor, boff);
    k_fill<<<(NE + B - 1) / B, B>>>(ei, cursor, csr);

    const int gemm128_grid = (NN + 63) / 64;
    const int agg_grid     = (NN + 7) / 8;   // 8 warps/block

    // Layer 1
    k_gemm128<false><<<gemm128_grid, 256>>>(x, W1, dinv, t, NN);
    k_agg128<false><<<agg_grid, 256>>>(rs, csr, t, dinv, b1, a, nullptr);
    // Layer 2
    k_gemm128<true><<<gemm128_grid, 256>>>(a, W2, dinv, t, NN);
    k_agg128<false><<<agg_grid, 256>>>(rs, csr, t, dinv, b2, a, nullptr);
    // Layer 3 (+ latent = relu(a))
    k_gemm128<true><<<gemm128_grid, 256>>>(a, W3, dinv, t, NN);
    k_agg128<true><<<agg_grid, 256>>>(rs, csr, t, dinv, b3, a, latent);
    // Layer 4
    k_gemm40<<<(NN + 31) / 32, 128>>>(a, W4, dinv, t, NN);
    k_agg40<<<agg_grid, 256>>>(rs, csr, t, dinv, b4, out);
}

// round 4
// speedup vs baseline: 2.1484x; 1.1573x over previous
#include <cuda_runtime.h>
#include <cuda_bf16.h>
#include <cuda_fp16.h>
#include <cstdint>

#define NN 100000
#define NE 1600000
#define NF 128
#define NC 40
#define NB_SCAN ((NN + 1023) / 1024)

// Scratch (device globals)
__device__ __align__(16) float g_dinv[NN];
__device__ __align__(16) __half g_th[(size_t)NN * NF];  // Y = dinv*(X@W) in fp16
__device__ __align__(16) float g_a[(size_t)NN * NF];    // aggregated activation (fp32)
__device__ int g_cnt[NN];
__device__ int g_rs[NN + 1];
__device__ int g_cursor[NN];
__device__ int g_csr[NE];
__device__ int g_bsum[NB_SCAN];
__device__ int g_boff[NB_SCAN];

// ---------------------------------------------------------------------------
// Packed fp32x2 helpers
// ---------------------------------------------------------------------------
__device__ __forceinline__ unsigned long long pack2(float x, float y) {
    unsigned long long r;
    asm("mov.b64 %0, {%1, %2};" : "=l"(r) : "f"(x), "f"(y));
    return r;
}
__device__ __forceinline__ void ffma2(unsigned long long& d,
                                      unsigned long long a, unsigned long long b) {
    asm("fma.rn.f32x2 %0, %1, %2, %0;" : "+l"(d) : "l"(a), "l"(b));
}
__device__ __forceinline__ float2 unpack2(unsigned long long v) {
    float2 r;
    asm("mov.b64 {%0, %1}, %2;" : "=f"(r.x), "=f"(r.y) : "l"(v));
    return r;
}

// 4 halves (uint2) -> float4
__device__ __forceinline__ float4 h4_to_f4(uint2 v) {
    __half2 a = *(__half2*)&v.x;
    __half2 b = *(__half2*)&v.y;
    float2 fa = __half22float2(a);
    float2 fb = __half22float2(b);
    return make_float4(fa.x, fa.y, fb.x, fb.y);
}

// ---------------------------------------------------------------------------
// CSR build
// ---------------------------------------------------------------------------
__global__ void k_zero(int* cnt) {
    int i = blockIdx.x * blockDim.x + threadIdx.x;
    if (i < NN) cnt[i] = 0;
}

__global__ void k_count(const int* __restrict__ ei, int* cnt) {
    int e = blockIdx.x * blockDim.x + threadIdx.x;
    if (e < NE) atomicAdd(&cnt[ei[NE + e]], 1);
}

__global__ void k_dinv(const int* __restrict__ cnt, float* dinv) {
    int i = blockIdx.x * blockDim.x + threadIdx.x;
    if (i < NN) dinv[i] = rsqrtf((float)(cnt[i] + 1));
}

__global__ void k_scan1(const int* __restrict__ cnt, int* rs, int* bsum) {
    __shared__ int s[1024];
    int i = blockIdx.x * 1024 + threadIdx.x;
    int v = (i < NN) ? cnt[i] : 0;
    s[threadIdx.x] = v;
    __syncthreads();
#pragma unroll
    for (int o = 1; o < 1024; o <<= 1) {
        int t = (threadIdx.x >= o) ? s[threadIdx.x - o] : 0;
        __syncthreads();
        s[threadIdx.x] += t;
        __syncthreads();
    }
    if (i < NN) rs[i] = s[threadIdx.x] - v;
    if (threadIdx.x == 1023) bsum[blockIdx.x] = s[1023];
}

__global__ void k_scan2(const int* __restrict__ bsum, int* boff) {
    __shared__ int s[NB_SCAN];
    if (threadIdx.x < NB_SCAN) s[threadIdx.x] = bsum[threadIdx.x];
    __syncthreads();
    if (threadIdx.x == 0) {
        int run = 0;
        for (int i = 0; i < NB_SCAN; i++) { int v = s[i]; s[i] = run; run += v; }
    }
    __syncthreads();
    if (threadIdx.x < NB_SCAN) boff[threadIdx.x] = s[threadIdx.x];
}

__global__ void k_scan3(int* rs, int* cursor, const int* __restrict__ boff) {
    int i = blockIdx.x * blockDim.x + threadIdx.x;
    if (i < NN) {
        int v = rs[i] + boff[i >> 10];
        rs[i] = v;
        cursor[i] = v;
    }
    if (i == 0) rs[NN] = NE;
}

__global__ void k_fill(const int* __restrict__ ei, int* cursor, int* csr) {
    int e = blockIdx.x * blockDim.x + threadIdx.x;
    if (e >= NE) return;
    int src = ei[e];
    int dst = ei[NE + e];
    int pos = atomicAdd(&cursor[dst], 1);
    csr[pos] = src;
}

// ---------------------------------------------------------------------------
// GEMM: Yh[M,128] = half( dinv[m] * (relu?(X[M,128]) @ W[128,128]) )
// ---------------------------------------------------------------------------
template <bool RELU>
__global__ void k_gemm128(const float* __restrict__ X, const float* __restrict__ W,
                          const float* __restrict__ dinv, __half* __restrict__ Yh, int M) {
    __shared__ float Xs[64][33];
    __shared__ float Ws[32][128];
    const int t  = threadIdx.x;
    const int m0 = blockIdx.x * 64;
    const int r0 = (t >> 5) * 8;
    const int c0 = (t & 31) * 4;

    unsigned long long acc2[8][2] = {};

    for (int k0 = 0; k0 < 128; k0 += 32) {
#pragma unroll
        for (int i = 0; i < 2; i++) {
            int idx = t + i * 256;
            int row = idx >> 3;
            int c4  = (idx & 7) * 4;
            float4 v = make_float4(0.f, 0.f, 0.f, 0.f);
            if (m0 + row < M)
                v = *(const float4*)&X[(size_t)(m0 + row) * 128 + k0 + c4];
            if (RELU) {
                v.x = fmaxf(v.x, 0.f); v.y = fmaxf(v.y, 0.f);
                v.z = fmaxf(v.z, 0.f); v.w = fmaxf(v.w, 0.f);
            }
            Xs[row][c4 + 0] = v.x; Xs[row][c4 + 1] = v.y;
            Xs[row][c4 + 2] = v.z; Xs[row][c4 + 3] = v.w;
        }
#pragma unroll
        for (int i = 0; i < 4; i++) {
            int idx = t + i * 256;
            int row = idx >> 5;
            int c4  = (idx & 31) * 4;
            *(float4*)&Ws[row][c4] = *(const float4*)&W[(size_t)(k0 + row) * 128 + c4];
        }
        __syncthreads();
#pragma unroll
        for (int kk = 0; kk < 32; kk++) {
            const unsigned long long* wp = (const unsigned long long*)&Ws[kk][c0];
            unsigned long long w01 = wp[0];
            unsigned long long w23 = wp[1];
#pragma unroll
            for (int i = 0; i < 8; i++) {
                float xv = Xs[r0 + i][kk];
                unsigned long long xp = pack2(xv, xv);
                ffma2(acc2[i][0], xp, w01);
                ffma2(acc2[i][1], xp, w23);
            }
        }
        __syncthreads();
    }
#pragma unroll
    for (int i = 0; i < 8; i++) {
        int row = m0 + r0 + i;
        if (row < M) {
            float d = __ldg(&dinv[row]);
            float2 a0 = unpack2(acc2[i][0]);
            float2 a1 = unpack2(acc2[i][1]);
            __half2 h0 = __float22half2_rn(make_float2(d * a0.x, d * a0.y));
            __half2 h1 = __float22half2_rn(make_float2(d * a1.x, d * a1.y));
            uint2 pkt;
            pkt.x = *(unsigned*)&h0;
            pkt.y = *(unsigned*)&h1;
            ((uint2*)Yh)[(size_t)row * 32 + (c0 >> 2)] = pkt;
        }
    }
}

// ---------------------------------------------------------------------------
// GEMM: Yh[M,40] = half( dinv[m] * (relu(X[M,128]) @ W[128,40]) )
// ---------------------------------------------------------------------------
__global__ void k_gemm40(const float* __restrict__ X, const float* __restrict__ W,
                         const float* __restrict__ dinv, __half* __restrict__ Yh, int M) {
    __shared__ float Xs[32][129];
    __shared__ float Ws[128 * 40];
    const int t  = threadIdx.x;
    const int m0 = blockIdx.x * 32;

    for (int i = t; i < 1280; i += 128)
        *(float4*)&Ws[i * 4] = *(const float4*)&W[(size_t)i * 4];

#pragma unroll
    for (int i = 0; i < 8; i++) {
        int idx = t + i * 128;
        int row = idx >> 5;
        int c4  = (idx & 31) * 4;
        float4 v = make_float4(0.f, 0.f, 0.f, 0.f);
        if (m0 + row < M)
            v = *(const float4*)&X[(size_t)(m0 + row) * 128 + c4];
        v.x = fmaxf(v.x, 0.f); v.y = fmaxf(v.y, 0.f);
        v.z = fmaxf(v.z, 0.f); v.w = fmaxf(v.w, 0.f);
        Xs[row][c4 + 0] = v.x; Xs[row][c4 + 1] = v.y;
        Xs[row][c4 + 2] = v.z; Xs[row][c4 + 3] = v.w;
    }
    __syncthreads();

    const int row = t >> 2;
    const int cg  = (t & 3) * 10;
    unsigned long long acc2[5] = {};
#pragma unroll 4
    for (int k = 0; k < 128; k++) {
        float xv = Xs[row][k];
        unsigned long long xp = pack2(xv, xv);
        const unsigned long long* wp = (const unsigned long long*)&Ws[k * 40 + cg];
#pragma unroll
        for (int j = 0; j < 5; j++)
            ffma2(acc2[j], xp, wp[j]);
    }
    int grow = m0 + row;
    if (grow < M) {
        float d = __ldg(&dinv[grow]);
#pragma unroll
        for (int j = 0; j < 5; j++) {
            float2 a = unpack2(acc2[j]);
            __half2 h = __float22half2_rn(make_float2(d * a.x, d * a.y));
            ((unsigned*)Yh)[(size_t)grow * 20 + (cg >> 1) + j] = *(unsigned*)&h;
        }
    }
}

// ---------------------------------------------------------------------------
// Aggregation gather (F=128): warp per node, fp16 messages, fp32 accumulate.
// ---------------------------------------------------------------------------
template <bool WRITE_LATENT>
__global__ void k_agg128(const int* __restrict__ rs, const int* __restrict__ csr,
                         const __half* __restrict__ Yh, const float* __restrict__ dinv,
                         const float* __restrict__ bias, float* __restrict__ A,
                         float* __restrict__ latent) {
    int node = blockIdx.x * (blockDim.x >> 5) + (threadIdx.x >> 5);
    if (node >= NN) return;
    int lane = threadIdx.x & 31;
    int beg = __ldg(&rs[node]);
    int end = __ldg(&rs[node + 1]);

    const uint2* Y4 = (const uint2*)Yh;  // 4 halves per lane element
    float4 acc = h4_to_f4(Y4[(size_t)node * 32 + lane]);  // self loop

    int j = beg;
    for (; j + 4 <= end; j += 4) {
        int s0 = __ldg(&csr[j]);
        int s1 = __ldg(&csr[j + 1]);
        int s2 = __ldg(&csr[j + 2]);
        int s3 = __ldg(&csr[j + 3]);
        float4 v0 = h4_to_f4(Y4[(size_t)s0 * 32 + lane]);
        float4 v1 = h4_to_f4(Y4[(size_t)s1 * 32 + lane]);
        float4 v2 = h4_to_f4(Y4[(size_t)s2 * 32 + lane]);
        float4 v3 = h4_to_f4(Y4[(size_t)s3 * 32 + lane]);
        acc.x += (v0.x + v1.x) + (v2.x + v3.x);
        acc.y += (v0.y + v1.y) + (v2.y + v3.y);
        acc.z += (v0.z + v1.z) + (v2.z + v3.z);
        acc.w += (v0.w + v1.w) + (v2.w + v3.w);
    }
    for (; j < end; j++) {
        int s = __ldg(&csr[j]);
        float4 v = h4_to_f4(Y4[(size_t)s * 32 + lane]);
        acc.x += v.x; acc.y += v.y; acc.z += v.z; acc.w += v.w;
    }

    float d = __ldg(&dinv[node]);
    float4 b = ((const float4*)bias)[lane];
    float4 o = make_float4(b.x + d * acc.x, b.y + d * acc.y,
                           b.z + d * acc.z, b.w + d * acc.w);
    ((float4*)A)[(size_t)node * 32 + lane] = o;
    if (WRITE_LATENT) {
        ((float4*)latent)[(size_t)node * 32 + lane] =
            make_float4(fmaxf(o.x, 0.f), fmaxf(o.y, 0.f),
                        fmaxf(o.z, 0.f), fmaxf(o.w, 0.f));
    }
}

// ---------------------------------------------------------------------------
// Aggregation gather (F=40): lanes 0..19 hold half2 -> float2 accumulate.
// ---------------------------------------------------------------------------
__global__ void k_agg40(const int* __restrict__ rs, const int* __restrict__ csr,
                        const __half* __restrict__ Yh, const float* __restrict__ dinv,
                        const float* __restrict__ bias, float* __restrict__ A) {
    int node = blockIdx.x * (blockDim.x >> 5) + (threadIdx.x >> 5);
    if (node >= NN) return;
    int lane = threadIdx.x & 31;
    int beg = __ldg(&rs[node]);
    int end = __ldg(&rs[node + 1]);
    bool act = lane < 20;

    const unsigned* Y2 = (const unsigned*)Yh;  // half2 per lane
    float2 acc = make_float2(0.f, 0.f);
    if (act) {
        unsigned u = Y2[(size_t)node * 20 + lane];
        float2 v = __half22float2(*(__half2*)&u);
        acc = v;
    }

    int j = beg;
    for (; j + 2 <= end; j += 2) {
        int s0 = __ldg(&csr[j]);
        int s1 = __ldg(&csr[j + 1]);
        if (act) {
            unsigned u0 = Y2[(size_t)s0 * 20 + lane];
            unsigned u1 = Y2[(size_t)s1 * 20 + lane];
            float2 v0 = __half22float2(*(__half2*)&u0);
            float2 v1 = __half22float2(*(__half2*)&u1);
            acc.x += v0.x + v1.x;
            acc.y += v0.y + v1.y;
        }
    }
    for (; j < end; j++) {
        int s = __ldg(&csr[j]);
        if (act) {
            unsigned u = Y2[(size_t)s * 20 + lane];
            float2 v = __half22float2(*(__half2*)&u);
            acc.x += v.x; acc.y += v.y;
        }
    }
    if (act) {
        float d = __ldg(&dinv[node]);
        float2 b = ((const float2*)bias)[lane];
        ((float2*)A)[(size_t)node * 20 + lane] =
            make_float2(b.x + d * acc.x, b.y + d * acc.y);
    }
}

// ---------------------------------------------------------------------------
// Launch
// ---------------------------------------------------------------------------
extern "C" void kernel_launch(void* const* d_in, const int* in_sizes, int n_in,
                              void* d_out, int out_size) {
    const float* x  = (const float*)d_in[0];
    const int*   ei = (const int*)d_in[1];
    const float* W1 = (const float*)d_in[2];
    const float* b1 = (const float*)d_in[3];
    const float* W2 = (const float*)d_in[4];
    const float* b2 = (const float*)d_in[5];
    const float* W3 = (const float*)d_in[6];
    const float* b3 = (const float*)d_in[7];
    const float* W4 = (const float*)d_in[8];
    const float* b4 = (const float*)d_in[9];

    float* out    = (float*)d_out;            // [NN, 40]
    float* latent = out + (size_t)NN * NC;    // [NN, 128]

    void *pdinv, *pth, *pa, *pcnt, *prs, *pcur, *pcsr, *pbs, *pbo;
    cudaGetSymbolAddress(&pdinv, g_dinv);
    cudaGetSymbolAddress(&pth,   g_th);
    cudaGetSymbolAddress(&pa,    g_a);
    cudaGetSymbolAddress(&pcnt,  g_cnt);
    cudaGetSymbolAddress(&prs,   g_rs);
    cudaGetSymbolAddress(&pcur,  g_cursor);
    cudaGetSymbolAddress(&pcsr,  g_csr);
    cudaGetSymbolAddress(&pbs,   g_bsum);
    cudaGetSymbolAddress(&pbo,   g_boff);
    float* dinv = (float*)pdinv;
    __half* th  = (__half*)pth;
    float* a    = (float*)pa;
    int* cnt    = (int*)pcnt;
    int* rs     = (int*)prs;
    int* cursor = (int*)pcur;
    int* csr    = (int*)pcsr;
    int* bsum   = (int*)pbs;
    int* boff   = (int*)pbo;

    const int B = 256;

    // --- CSR build + normalization ---
    k_zero<<<(NN + B - 1) / B, B>>>(cnt);
    k_count<<<(NE + B - 1) / B, B>>>(ei, cnt);
    k_dinv<<<(NN + B - 1) / B, B>>>(cnt, dinv);
    k_scan1<<<NB_SCAN, 1024>>>(cnt, rs, bsum);
    k_scan2<<<1, 128>>>(bsum, boff);
    k_scan3<<<(NN + B - 1) / B, B>>>(rs, cursor, boff);
    k_fill<<<(NE + B - 1) / B, B>>>(ei, cursor, csr);

    const int gemm128_grid = (NN + 63) / 64;
    const int agg_grid     = (NN + 7) / 8;

    // Layer 1
    k_gemm128<false><<<gemm128_grid, 256>>>(x, W1, dinv, th, NN);
    k_agg128<false><<<agg_grid, 256>>>(rs, csr, th, dinv, b1, a, nullptr);
    // Layer 2
    k_gemm128<true><<<gemm128_grid, 256>>>(a, W2, dinv, th, NN);
    k_agg128<false><<<agg_grid, 256>>>(rs, csr, th, dinv, b2, a, nullptr);
    // Layer 3 (+ latent)
    k_gemm128<true><<<gemm128_grid, 256>>>(a, W3, dinv, th, NN);
    k_agg128<true><<<agg_grid, 256>>>(rs, csr, th, dinv, b3, a, latent);
    // Layer 4
    k_gemm40<<<(NN + 31) / 32, 128>>>(a, W4, dinv, th, NN);
    k_agg40<<<agg_grid, 256>>>(rs, csr, th, dinv, b4, out);
}